// round 15
// baseline (speedup 1.0000x reference)
#include <cuda_runtime.h>
#include <cuda_fp16.h>
#include <cstdint>

#define TPB    128
#define BM     128
#define H      128
#define LDAH   136          // fp16 tile row pitch in halves (272B)
#define ROWB   272
#define LN_EPS 1e-5f

// ---- edge-kernel SMEM layout (bytes) ----
#define SM_PAR   0          // 1281 floats of params
#define SM_A     5632       // fp16 edge A tile (34816)
#define SM_B     40448      // weight buffer 0 (34816)
#define SM_B2    75264      // weight buffer 1 (34816)
#define SM_TOTAL 110080

// ---- node-kernel SMEM layout ----
#define NSM_A    0
#define NSM_B0   34816
#define NSM_B1   69632
#define NSM_TOT  104448

#define Y2OFF 12800000      // offset of y2 table inside g_y

// 5 pre-transposed fp16 weight tiles [tile][n=128][k=128]:
// tiles 0,1,2 = W0 k-chunks (W0a,W0b,W0c), 3 = W1, 4 = W2
__device__ __align__(16) __half g_wt[5 * 16384];
// node projections: y1 = x@W0a (floats [0,12.8M)), y2 = x@W0b ([Y2OFF, +12.8M))
__device__ __align__(16) float g_y[2 * 12800000];

__device__ __forceinline__ uint32_t smem_u32(const void* p) {
    uint32_t a;
    asm("{ .reg .u64 t; cvta.to.shared.u64 t, %1; cvt.u32.u64 %0, t; }"
        : "=r"(a) : "l"(p));
    return a;
}

#define LDMATRIX_X4(r0, r1, r2, r3, addr)                                      \
    asm volatile("ldmatrix.sync.aligned.m8n8.x4.shared.b16 {%0,%1,%2,%3}, [%4];" \
                 : "=r"(r0), "=r"(r1), "=r"(r2), "=r"(r3) : "r"(addr))

#define MMA16816(d, a0, a1, a2, a3, bb0, bb1)                                  \
    asm volatile("mma.sync.aligned.m16n8k16.row.col.f32.f16.f16.f32 "          \
                 "{%0,%1,%2,%3}, {%4,%5,%6,%7}, {%8,%9}, {%0,%1,%2,%3};"       \
                 : "+f"((d)[0]), "+f"((d)[1]), "+f"((d)[2]), "+f"((d)[3])      \
                 : "r"(a0), "r"(a1), "r"(a2), "r"(a3), "r"(bb0), "r"(bb1))

#define CP_ASYNC16(dst, src)                                                   \
    asm volatile("cp.async.cg.shared.global [%0], [%1], 16;" :: "r"(dst), "l"(src))
#define CP_COMMIT()  asm volatile("cp.async.commit_group;" ::: "memory")
#define CP_WAIT0()   asm volatile("cp.async.wait_group 0;" ::: "memory")

// B-fragment SMEM offset for MMA group t (t = ks*8 + g)
#define BOFF(t) ((uint32_t)(((t) & 7) * (16 * ROWB) + ((t) >> 3) * 32))

// ---------------- prep: transpose + fp16-convert weights ----------------
__global__ void prep_w(const float* __restrict__ W0,
                       const float* __restrict__ W1,
                       const float* __restrict__ W2) {
    int idx = blockIdx.x * blockDim.x + threadIdx.x;
    if (idx >= 5 * 16384) return;
    int t = idx >> 14, r = idx & 16383, n = r >> 7, k = r & 127;
    float v;
    if (t < 3)       v = W0[(t * 128 + k) * 128 + n];
    else if (t == 3) v = W1[k * 128 + n];
    else             v = W2[k * 128 + n];
    g_wt[idx] = __float2half_rn(v);
}

// ---------------- node kernel: y1 = x@W0a, y2 = x@W0b ----------------
extern "C" __global__ void __launch_bounds__(TPB, 2)
prep_y(const float* __restrict__ x, int N) {
    extern __shared__ char smem[];
    const uint32_t sb = smem_u32(smem);
    const int tid = threadIdx.x, wid = tid >> 5, lane = tid & 31;
    const int base = blockIdx.x * BM;

    const int arow = (lane & 7) + ((lane >> 3) & 1) * 8;
    const int acol = (lane >> 4) * 8;
    const uint32_t aaddr0 = sb + NSM_A + (uint32_t)((wid * 32 + arow) * LDAH + acol) * 2;
    const uint32_t aaddr1 = aaddr0 + 16 * ROWB;
    const int bn = (lane & 7) + ((lane >> 4) & 1) * 8;
    const int bk = ((lane >> 3) & 1) * 8;
    const uint32_t blane = (uint32_t)(bn * LDAH + bk) * 2;

    float acc[2][16][4];
    auto zero_acc = [&]() {
#pragma unroll
        for (int a = 0; a < 2; a++)
#pragma unroll
            for (int t = 0; t < 16; t++)
#pragma unroll
                for (int j = 0; j < 4; j++) acc[a][t][j] = 0.f;
    };

    auto stage_b = [&](int t, uint32_t dstOff) {
        const char* src = (const char*)(g_wt + t * 16384);
        uint32_t dst = sb + dstOff;
#pragma unroll
        for (int i = 0; i < 16; i++) {
            int u = tid + i * TPB;
            CP_ASYNC16(dst + (u >> 4) * ROWB + (u & 15) * 16, src + u * 16);
        }
        CP_COMMIT();
    };

    auto mma_pass = [&](uint32_t bufAbs) {
        uint32_t A0[4], A1[4], N0[4], N1[4], Bf[3][4];
        uint32_t bb = sb + bufAbs + blane;
        LDMATRIX_X4(A0[0], A0[1], A0[2], A0[3], aaddr0);
        LDMATRIX_X4(A1[0], A1[1], A1[2], A1[3], aaddr1);
        LDMATRIX_X4(Bf[0][0], Bf[0][1], Bf[0][2], Bf[0][3], bb + BOFF(0));
        LDMATRIX_X4(Bf[1][0], Bf[1][1], Bf[1][2], Bf[1][3], bb + BOFF(1));
#pragma unroll
        for (int ks = 0; ks < 8; ks++) {
            if (ks < 7) {
                LDMATRIX_X4(N0[0], N0[1], N0[2], N0[3], aaddr0 + (ks + 1) * 32);
                LDMATRIX_X4(N1[0], N1[1], N1[2], N1[3], aaddr1 + (ks + 1) * 32);
            }
#pragma unroll
            for (int g = 0; g < 8; g++) {
                int t = ks * 8 + g;
                if (t < 62) {
                    int nt = t + 2;
                    LDMATRIX_X4(Bf[nt % 3][0], Bf[nt % 3][1],
                                Bf[nt % 3][2], Bf[nt % 3][3], bb + BOFF(nt));
                }
                const uint32_t* Bc = Bf[t % 3];
                MMA16816(acc[0][2 * g],     A0[0], A0[1], A0[2], A0[3], Bc[0], Bc[1]);
                MMA16816(acc[0][2 * g + 1], A0[0], A0[1], A0[2], A0[3], Bc[2], Bc[3]);
                MMA16816(acc[1][2 * g],     A1[0], A1[1], A1[2], A1[3], Bc[0], Bc[1]);
                MMA16816(acc[1][2 * g + 1], A1[0], A1[1], A1[2], A1[3], Bc[2], Bc[3]);
            }
#pragma unroll
            for (int i = 0; i < 4; i++) { A0[i] = N0[i]; A1[i] = N1[i]; }
        }
    };

    const int c2 = 2 * (lane & 3);
    const int r4 = lane >> 2;

    auto write_y = [&](size_t yoff) {
#pragma unroll
        for (int am = 0; am < 2; am++)
#pragma unroll
            for (int h = 0; h < 2; h++) {
                int row = wid * 32 + am * 16 + h * 8 + r4;
                int node = base + row;
                if (node < N) {
                    float* dst = g_y + yoff + (size_t)node * H;
#pragma unroll
                    for (int nt = 0; nt < 16; nt++) {
                        *(float2*)(dst + nt * 8 + c2) =
                            make_float2(acc[am][nt][2 * h], acc[am][nt][2 * h + 1]);
                    }
                }
            }
    };

    stage_b(0, NSM_B0);
#pragma unroll
    for (int r = 0; r < 32; r++) {
        int m = wid * 32 + r;
        int node = base + m; if (node >= N) node = N - 1;
        float4 v = __ldcs((const float4*)(x + (size_t)node * H) + lane);
        __half2 h0 = __floats2half2_rn(v.x, v.y);
        __half2 h1 = __floats2half2_rn(v.z, v.w);
        *(uint2*)(smem + NSM_A + m * ROWB + lane * 8) =
            make_uint2(*(uint32_t*)&h0, *(uint32_t*)&h1);
    }
    __syncwarp();
    CP_WAIT0(); __syncthreads();            // B0 (W0a) ready

    stage_b(1, NSM_B1);
    zero_acc();
    mma_pass(NSM_B0);
    write_y(0);                              // y1
    CP_WAIT0(); __syncthreads();             // B1 (W0b) ready

    zero_acc();
    mma_pass(NSM_B1);
    write_y(Y2OFF);                          // y2
}

// ---------------- main fused edge kernel ----------------
extern "C" __global__ void __launch_bounds__(TPB, 2)
edge_mlp_hmma13(float* __restrict__ out,
                const int* __restrict__ ei,
                const float* __restrict__ edge,
                const float* __restrict__ b0, const float* __restrict__ g0, const float* __restrict__ be0,
                const float* __restrict__ b1, const float* __restrict__ g1, const float* __restrict__ be1,
                const float* __restrict__ b2, const float* __restrict__ g2, const float* __restrict__ be2,
                const float* __restrict__ W3, const float* __restrict__ b3,
                int E) {
    extern __shared__ char smem[];
    float* smf = (float*)smem;
    const uint32_t sb = smem_u32(smem);
    const int tid = threadIdx.x, wid = tid >> 5, lane = tid & 31;
    const int base = blockIdx.x * BM;

    // stage LN params + W3/b3 (fp32)
    {
        int i = tid;
        smf[0 * 384 + i] = b0[i]; smf[0 * 384 + 128 + i] = g0[i]; smf[0 * 384 + 256 + i] = be0[i];
        smf[1 * 384 + i] = b1[i]; smf[1 * 384 + 128 + i] = g1[i]; smf[1 * 384 + 256 + i] = be1[i];
        smf[2 * 384 + i] = b2[i]; smf[2 * 384 + 128 + i] = g2[i]; smf[2 * 384 + 256 + i] = be2[i];
        smf[1152 + i] = W3[i];
    }
    if (tid == 0) smf[1280] = b3[0];

    const int arow = (lane & 7) + ((lane >> 3) & 1) * 8;
    const int acol = (lane >> 4) * 8;
    const uint32_t aaddr0 = sb + SM_A + (uint32_t)((wid * 32 + arow) * LDAH + acol) * 2;
    const uint32_t aaddr1 = aaddr0 + 16 * ROWB;
    const int bn = (lane & 7) + ((lane >> 4) & 1) * 8;
    const int bk = ((lane >> 3) & 1) * 8;
    const uint32_t blane = (uint32_t)(bn * LDAH + bk) * 2;

    const int c2 = 2 * (lane & 3);
    const int r4 = lane >> 2;

    float acc[2][16][4];
    uint32_t ah[2][16][2];

    auto zero_acc = [&]() {
#pragma unroll
        for (int a = 0; a < 2; a++)
#pragma unroll
            for (int t = 0; t < 16; t++)
#pragma unroll
                for (int j = 0; j < 4; j++) acc[a][t][j] = 0.f;
    };

    // acc = y1[src] + y2[dst], loaded straight into the fragment layout.
    // Thread's 4 row-slots (am,h); cols nt*8 + c2 (+1). Quad-coherent 32B sectors.
    auto init_acc_ysum = [&]() {
#pragma unroll
        for (int am = 0; am < 2; am++)
#pragma unroll
            for (int h = 0; h < 2; h++) {
                int row = wid * 32 + am * 16 + h * 8 + r4;
                int e = base + row; if (e >= E) e = E - 1;
                int s = __ldcs(&ei[e]);
                int d = __ldcs(&ei[(size_t)E + e]);
                const float2* p1 = (const float2*)(g_y + (size_t)s * H) + (lane & 3);
                const float2* p2 = (const float2*)(g_y + Y2OFF + (size_t)d * H) + (lane & 3);
#pragma unroll
                for (int nt = 0; nt < 16; nt++) {
                    float2 a = __ldg(p1 + nt * 4);
                    float2 b = __ldg(p2 + nt * 4);
                    acc[am][nt][2 * h]     = a.x + b.x;
                    acc[am][nt][2 * h + 1] = a.y + b.y;
                }
            }
    };

    auto stage_b = [&](int t, uint32_t dstOff) {
        const char* src = (const char*)(g_wt + t * 16384);
        uint32_t dst = sb + dstOff;
#pragma unroll
        for (int i = 0; i < 16; i++) {
            int u = tid + i * TPB;
            CP_ASYNC16(dst + (u >> 4) * ROWB + (u & 15) * 16, src + u * 16);
        }
        CP_COMMIT();
    };

    // gather edge rows (fp32 -> fp16), warp-local rows; single-use -> streaming
    auto gather_edge = [&]() {
#pragma unroll
        for (int r = 0; r < 32; r++) {
            int m = wid * 32 + r;
            int e = base + m; if (e >= E) e = E - 1;
            float4 v = __ldcs((const float4*)(edge + (size_t)e * H) + lane);
            __half2 h0 = __floats2half2_rn(v.x, v.y);
            __half2 h1 = __floats2half2_rn(v.z, v.w);
            *(uint2*)(smem + SM_A + m * ROWB + lane * 8) =
                make_uint2(*(uint32_t*)&h0, *(uint32_t*)&h1);
        }
        __syncwarp();
    };

    // layer-0 MMA: A streamed from SMEM, B ring depth 3 (accumulates onto ysum)
    auto mma_l0 = [&](uint32_t bufAbs) {
        uint32_t A0[4], A1[4], N0[4], N1[4], Bf[3][4];
        uint32_t bb = sb + bufAbs + blane;
        LDMATRIX_X4(A0[0], A0[1], A0[2], A0[3], aaddr0);
        LDMATRIX_X4(A1[0], A1[1], A1[2], A1[3], aaddr1);
        LDMATRIX_X4(Bf[0][0], Bf[0][1], Bf[0][2], Bf[0][3], bb + BOFF(0));
        LDMATRIX_X4(Bf[1][0], Bf[1][1], Bf[1][2], Bf[1][3], bb + BOFF(1));
#pragma unroll
        for (int ks = 0; ks < 8; ks++) {
            if (ks < 7) {
                LDMATRIX_X4(N0[0], N0[1], N0[2], N0[3], aaddr0 + (ks + 1) * 32);
                LDMATRIX_X4(N1[0], N1[1], N1[2], N1[3], aaddr1 + (ks + 1) * 32);
            }
#pragma unroll
            for (int g = 0; g < 8; g++) {
                int t = ks * 8 + g;
                if (t < 62) {
                    int nt = t + 2;
                    LDMATRIX_X4(Bf[nt % 3][0], Bf[nt % 3][1],
                                Bf[nt % 3][2], Bf[nt % 3][3], bb + BOFF(nt));
                }
                const uint32_t* Bc = Bf[t % 3];
                MMA16816(acc[0][2 * g],     A0[0], A0[1], A0[2], A0[3], Bc[0], Bc[1]);
                MMA16816(acc[0][2 * g + 1], A0[0], A0[1], A0[2], A0[3], Bc[2], Bc[3]);
                MMA16816(acc[1][2 * g],     A1[0], A1[1], A1[2], A1[3], Bc[0], Bc[1]);
                MMA16816(acc[1][2 * g + 1], A1[0], A1[1], A1[2], A1[3], Bc[2], Bc[3]);
            }
#pragma unroll
            for (int i = 0; i < 4; i++) { A0[i] = N0[i]; A1[i] = N1[i]; }
        }
    };

    // layers 1-2 MMA: A from ah registers, B ring depth 3
    auto mma_reg = [&](uint32_t bufAbs) {
        uint32_t Bf[3][4];
        uint32_t bb = sb + bufAbs + blane;
        LDMATRIX_X4(Bf[0][0], Bf[0][1], Bf[0][2], Bf[0][3], bb + BOFF(0));
        LDMATRIX_X4(Bf[1][0], Bf[1][1], Bf[1][2], Bf[1][3], bb + BOFF(1));
#pragma unroll
        for (int ks = 0; ks < 8; ks++) {
#pragma unroll
            for (int g = 0; g < 8; g++) {
                int t = ks * 8 + g;
                if (t < 62) {
                    int nt = t + 2;
                    LDMATRIX_X4(Bf[nt % 3][0], Bf[nt % 3][1],
                                Bf[nt % 3][2], Bf[nt % 3][3], bb + BOFF(nt));
                }
                const uint32_t* Bc = Bf[t % 3];
                MMA16816(acc[0][2 * g],     ah[0][2 * ks][0], ah[0][2 * ks][1],
                         ah[0][2 * ks + 1][0], ah[0][2 * ks + 1][1], Bc[0], Bc[1]);
                MMA16816(acc[0][2 * g + 1], ah[0][2 * ks][0], ah[0][2 * ks][1],
                         ah[0][2 * ks + 1][0], ah[0][2 * ks + 1][1], Bc[2], Bc[3]);
                MMA16816(acc[1][2 * g],     ah[1][2 * ks][0], ah[1][2 * ks][1],
                         ah[1][2 * ks + 1][0], ah[1][2 * ks + 1][1], Bc[0], Bc[1]);
                MMA16816(acc[1][2 * g + 1], ah[1][2 * ks][0], ah[1][2 * ks][1],
                         ah[1][2 * ks + 1][0], ah[1][2 * ks + 1][1], Bc[2], Bc[3]);
            }
        }
    };

    // warp-local LN epilogue.
    auto epilogue = [&](int l, bool last) {
        const float* pb = smf + l * 384;
        const float* pg = pb + 128;
        const float* pe = pb + 256;
        float s1[2][2], s2[2][2];
#pragma unroll
        for (int am = 0; am < 2; am++)
#pragma unroll
            for (int h = 0; h < 2; h++) { s1[am][h] = 0.f; s2[am][h] = 0.f; }
#pragma unroll
        for (int nt = 0; nt < 16; nt++) {
            int n0 = nt * 8 + c2;
            float bia0 = pb[n0], bia1 = pb[n0 + 1];
#pragma unroll
            for (int am = 0; am < 2; am++)
#pragma unroll
                for (int h = 0; h < 2; h++) {
                    float v0 = acc[am][nt][2 * h]     + bia0;
                    float v1 = acc[am][nt][2 * h + 1] + bia1;
                    acc[am][nt][2 * h] = v0; acc[am][nt][2 * h + 1] = v1;
                    s1[am][h] += v0 + v1;
                    s2[am][h] += v0 * v0 + v1 * v1;
                }
        }
#pragma unroll
        for (int o = 1; o <= 2; o <<= 1)
#pragma unroll
            for (int am = 0; am < 2; am++)
#pragma unroll
                for (int h = 0; h < 2; h++) {
                    s1[am][h] += __shfl_xor_sync(0xffffffffu, s1[am][h], o);
                    s2[am][h] += __shfl_xor_sync(0xffffffffu, s2[am][h], o);
                }
        float mu[2][2], rs[2][2];
#pragma unroll
        for (int am = 0; am < 2; am++)
#pragma unroll
            for (int h = 0; h < 2; h++) {
                float m_ = s1[am][h] * (1.0f / 128.0f);
                mu[am][h] = m_;
                rs[am][h] = rsqrtf(s2[am][h] * (1.0f / 128.0f) - m_ * m_ + LN_EPS);
            }
        if (!last) {
#pragma unroll
            for (int nt = 0; nt < 16; nt++) {
                int n0 = nt * 8 + c2;
                float ga0 = pg[n0], ga1 = pg[n0 + 1];
                float ea0 = pe[n0], ea1 = pe[n0 + 1];
#pragma unroll
                for (int am = 0; am < 2; am++) {
#pragma unroll
                    for (int h = 0; h < 2; h++) {
                        float v0 = fmaxf((acc[am][nt][2 * h]     - mu[am][h]) * rs[am][h] * ga0 + ea0, 0.f);
                        float v1 = fmaxf((acc[am][nt][2 * h + 1] - mu[am][h]) * rs[am][h] * ga1 + ea1, 0.f);
                        __half2 hv = __floats2half2_rn(v0, v1);
                        ah[am][nt][h] = *(uint32_t*)&hv;
                    }
                }
            }
        } else {
            const float* w3 = smf + 1152;
            float p[2][2];
#pragma unroll
            for (int am = 0; am < 2; am++)
#pragma unroll
                for (int h = 0; h < 2; h++) p[am][h] = 0.f;
#pragma unroll
            for (int nt = 0; nt < 16; nt++) {
                int n0 = nt * 8 + c2;
                float ga0 = pg[n0], ga1 = pg[n0 + 1];
                float ea0 = pe[n0], ea1 = pe[n0 + 1];
                float w30 = w3[n0], w31 = w3[n0 + 1];
#pragma unroll
                for (int am = 0; am < 2; am++)
#pragma unroll
                    for (int h = 0; h < 2; h++) {
                        p[am][h] += fmaxf((acc[am][nt][2 * h]     - mu[am][h]) * rs[am][h] * ga0 + ea0, 0.f) * w30
                                  + fmaxf((acc[am][nt][2 * h + 1] - mu[am][h]) * rs[am][h] * ga1 + ea1, 0.f) * w31;
                    }
            }
#pragma unroll
            for (int o = 1; o <= 2; o <<= 1)
#pragma unroll
                for (int am = 0; am < 2; am++)
#pragma unroll
                    for (int h = 0; h < 2; h++)
                        p[am][h] += __shfl_xor_sync(0xffffffffu, p[am][h], o);
            if ((lane & 3) == 0) {
                float bb3 = smf[1280];
#pragma unroll
                for (int am = 0; am < 2; am++)
#pragma unroll
                    for (int h = 0; h < 2; h++) {
                        int row = wid * 32 + am * 16 + h * 8 + r4;
                        int e = base + row;
                        if (e < E) __stcs(&out[e], p[am][h] + bb3);
                    }
            }
        }
    };

    // ---------------- pipeline ----------------
    stage_b(2, SM_B);                  // W0c
    gather_edge();                     // edge -> A (fp16)
    init_acc_ysum();                   // acc = y1[src]+y2[dst] (L2 hits, overlaps)
    CP_WAIT0(); __syncthreads();       // W0c ready

    stage_b(3, SM_B2);                 // W1 streams during layer-0 MMA
    mma_l0(SM_B);                      // acc += edge @ W0c
    epilogue(0, false);                // +b0, LN, ReLU -> ah (warp-local)
    CP_WAIT0(); __syncthreads();       // W1 ready; all warps past mma(SM_B)

    stage_b(4, SM_B);                  // W2 streams during layer-1 MMA
    zero_acc();
    mma_reg(SM_B2);                    // W1
    epilogue(1, false);
    CP_WAIT0(); __syncthreads();       // W2 ready; all past mma(SM_B2)

    zero_acc();
    mma_reg(SM_B);                     // W2
    epilogue(2, true);
}

extern "C" void kernel_launch(void* const* d_in, const int* in_sizes, int n_in,
                              void* d_out, int out_size) {
    const float* x    = (const float*)d_in[0];
    const int*   ei   = (const int*)d_in[1];
    const float* edge = (const float*)d_in[2];
    const float* W0   = (const float*)d_in[3];
    const float* b0   = (const float*)d_in[4];
    const float* g0   = (const float*)d_in[5];
    const float* be0  = (const float*)d_in[6];
    const float* W1   = (const float*)d_in[7];
    const float* b1   = (const float*)d_in[8];
    const float* g1   = (const float*)d_in[9];
    const float* be1  = (const float*)d_in[10];
    const float* W2   = (const float*)d_in[11];
    const float* b2   = (const float*)d_in[12];
    const float* g2   = (const float*)d_in[13];
    const float* be2  = (const float*)d_in[14];
    const float* W3   = (const float*)d_in[15];
    const float* b3   = (const float*)d_in[16];

    int E = out_size;
    int N = in_sizes[0] / H;     // number of nodes

    prep_w<<<(5 * 16384 + 255) / 256, 256>>>(W0, W1, W2);

    cudaFuncSetAttribute(prep_y,
                         cudaFuncAttributeMaxDynamicSharedMemorySize, NSM_TOT);
    prep_y<<<(N + BM - 1) / BM, TPB, NSM_TOT>>>(x, N);

    cudaFuncSetAttribute(edge_mlp_hmma13,
                         cudaFuncAttributeMaxDynamicSharedMemorySize, SM_TOTAL);
    dim3 grid((E + BM - 1) / BM);
    edge_mlp_hmma13<<<grid, TPB, SM_TOTAL>>>(
        (float*)d_out, ei, edge,
        b0, g0, be0, b1, g1, be1, b2, g2, be2, W3, b3, E);
}

// round 16
// speedup vs baseline: 1.3186x; 1.3186x over previous
#include <cuda_runtime.h>
#include <cuda_fp16.h>
#include <cstdint>

#define TPB    128
#define BM     128
#define H      128
#define LDAH   136          // fp16 tile row pitch in halves (272B)
#define ROWB   272
#define LN_EPS 1e-5f

// ---- edge-kernel SMEM layout (bytes) ----
#define SM_PAR   0          // 1281 floats of params
#define SM_A     5632       // fp16 edge A tile (34816); W1 staged here after layer 0
#define SM_YS    40448      // fp16 ysum tile, 272B pitch (34816)
#define SM_B     75264      // weight buffer (34816)
#define SM_TOTAL 110080

// ---- node-kernel SMEM layout ----
#define NSM_A    0
#define NSM_B0   34816
#define NSM_B1   69632
#define NSM_TOT  104448

#define Y2OFF 12800000      // offset (in halves) of y2 table inside g_yh

// 5 pre-transposed fp16 weight tiles [tile][n=128][k=128]:
// tiles 0,1,2 = W0 k-chunks (W0a,W0b,W0c), 3 = W1, 4 = W2
__device__ __align__(16) __half g_wt[5 * 16384];
// node projections in fp16: y1 = x@W0a, y2 = x@W0b  (51.2MB total, L2-resident)
__device__ __align__(16) __half g_yh[2 * 12800000];

__device__ __forceinline__ uint32_t smem_u32(const void* p) {
    uint32_t a;
    asm("{ .reg .u64 t; cvta.to.shared.u64 t, %1; cvt.u32.u64 %0, t; }"
        : "=r"(a) : "l"(p));
    return a;
}

#define LDMATRIX_X4(r0, r1, r2, r3, addr)                                      \
    asm volatile("ldmatrix.sync.aligned.m8n8.x4.shared.b16 {%0,%1,%2,%3}, [%4];" \
                 : "=r"(r0), "=r"(r1), "=r"(r2), "=r"(r3) : "r"(addr))

#define MMA16816(d, a0, a1, a2, a3, bb0, bb1)                                  \
    asm volatile("mma.sync.aligned.m16n8k16.row.col.f32.f16.f16.f32 "          \
                 "{%0,%1,%2,%3}, {%4,%5,%6,%7}, {%8,%9}, {%0,%1,%2,%3};"       \
                 : "+f"((d)[0]), "+f"((d)[1]), "+f"((d)[2]), "+f"((d)[3])      \
                 : "r"(a0), "r"(a1), "r"(a2), "r"(a3), "r"(bb0), "r"(bb1))

#define CP_ASYNC16(dst, src)                                                   \
    asm volatile("cp.async.cg.shared.global [%0], [%1], 16;" :: "r"(dst), "l"(src))
#define CP_COMMIT()  asm volatile("cp.async.commit_group;" ::: "memory")
#define CP_WAIT0()   asm volatile("cp.async.wait_group 0;" ::: "memory")

// B-fragment SMEM offset for MMA group t (t = ks*8 + g)
#define BOFF(t) ((uint32_t)(((t) & 7) * (16 * ROWB) + ((t) >> 3) * 32))

// ---------------- prep: transpose + fp16-convert weights ----------------
__global__ void prep_w(const float* __restrict__ W0,
                       const float* __restrict__ W1,
                       const float* __restrict__ W2) {
    int idx = blockIdx.x * blockDim.x + threadIdx.x;
    if (idx >= 5 * 16384) return;
    int t = idx >> 14, r = idx & 16383, n = r >> 7, k = r & 127;
    float v;
    if (t < 3)       v = W0[(t * 128 + k) * 128 + n];
    else if (t == 3) v = W1[k * 128 + n];
    else             v = W2[k * 128 + n];
    g_wt[idx] = __float2half_rn(v);
}

// ---------------- node kernel: y1 = x@W0a, y2 = x@W0b (fp16 out) ----------------
extern "C" __global__ void __launch_bounds__(TPB, 2)
prep_y(const float* __restrict__ x, int N) {
    extern __shared__ char smem[];
    const uint32_t sb = smem_u32(smem);
    const int tid = threadIdx.x, wid = tid >> 5, lane = tid & 31;
    const int base = blockIdx.x * BM;

    const int arow = (lane & 7) + ((lane >> 3) & 1) * 8;
    const int acol = (lane >> 4) * 8;
    const uint32_t aaddr0 = sb + NSM_A + (uint32_t)((wid * 32 + arow) * LDAH + acol) * 2;
    const uint32_t aaddr1 = aaddr0 + 16 * ROWB;
    const int bn = (lane & 7) + ((lane >> 4) & 1) * 8;
    const int bk = ((lane >> 3) & 1) * 8;
    const uint32_t blane = (uint32_t)(bn * LDAH + bk) * 2;

    float acc[2][16][4];
    auto zero_acc = [&]() {
#pragma unroll
        for (int a = 0; a < 2; a++)
#pragma unroll
            for (int t = 0; t < 16; t++)
#pragma unroll
                for (int j = 0; j < 4; j++) acc[a][t][j] = 0.f;
    };

    auto stage_b = [&](int t, uint32_t dstOff) {
        const char* src = (const char*)(g_wt + t * 16384);
        uint32_t dst = sb + dstOff;
#pragma unroll
        for (int i = 0; i < 16; i++) {
            int u = tid + i * TPB;
            CP_ASYNC16(dst + (u >> 4) * ROWB + (u & 15) * 16, src + u * 16);
        }
        CP_COMMIT();
    };

    auto mma_pass = [&](uint32_t bufAbs) {
        uint32_t A0[4], A1[4], N0[4], N1[4], Bf[3][4];
        uint32_t bb = sb + bufAbs + blane;
        LDMATRIX_X4(A0[0], A0[1], A0[2], A0[3], aaddr0);
        LDMATRIX_X4(A1[0], A1[1], A1[2], A1[3], aaddr1);
        LDMATRIX_X4(Bf[0][0], Bf[0][1], Bf[0][2], Bf[0][3], bb + BOFF(0));
        LDMATRIX_X4(Bf[1][0], Bf[1][1], Bf[1][2], Bf[1][3], bb + BOFF(1));
#pragma unroll
        for (int ks = 0; ks < 8; ks++) {
            if (ks < 7) {
                LDMATRIX_X4(N0[0], N0[1], N0[2], N0[3], aaddr0 + (ks + 1) * 32);
                LDMATRIX_X4(N1[0], N1[1], N1[2], N1[3], aaddr1 + (ks + 1) * 32);
            }
#pragma unroll
            for (int g = 0; g < 8; g++) {
                int t = ks * 8 + g;
                if (t < 62) {
                    int nt = t + 2;
                    LDMATRIX_X4(Bf[nt % 3][0], Bf[nt % 3][1],
                                Bf[nt % 3][2], Bf[nt % 3][3], bb + BOFF(nt));
                }
                const uint32_t* Bc = Bf[t % 3];
                MMA16816(acc[0][2 * g],     A0[0], A0[1], A0[2], A0[3], Bc[0], Bc[1]);
                MMA16816(acc[0][2 * g + 1], A0[0], A0[1], A0[2], A0[3], Bc[2], Bc[3]);
                MMA16816(acc[1][2 * g],     A1[0], A1[1], A1[2], A1[3], Bc[0], Bc[1]);
                MMA16816(acc[1][2 * g + 1], A1[0], A1[1], A1[2], A1[3], Bc[2], Bc[3]);
            }
#pragma unroll
            for (int i = 0; i < 4; i++) { A0[i] = N0[i]; A1[i] = N1[i]; }
        }
    };

    const int c2 = 2 * (lane & 3);
    const int r4 = lane >> 2;

    auto write_y = [&](size_t yoff) {
#pragma unroll
        for (int am = 0; am < 2; am++)
#pragma unroll
            for (int h = 0; h < 2; h++) {
                int row = wid * 32 + am * 16 + h * 8 + r4;
                int node = base + row;
                if (node < N) {
                    __half* dst = g_yh + yoff + (size_t)node * H;
#pragma unroll
                    for (int nt = 0; nt < 16; nt++) {
                        __half2 hv = __floats2half2_rn(acc[am][nt][2 * h],
                                                       acc[am][nt][2 * h + 1]);
                        *(uint32_t*)(dst + nt * 8 + c2) = *(uint32_t*)&hv;
                    }
                }
            }
    };

    stage_b(0, NSM_B0);
#pragma unroll
    for (int r = 0; r < 32; r++) {
        int m = wid * 32 + r;
        int node = base + m; if (node >= N) node = N - 1;
        float4 v = __ldcs((const float4*)(x + (size_t)node * H) + lane);
        __half2 h0 = __floats2half2_rn(v.x, v.y);
        __half2 h1 = __floats2half2_rn(v.z, v.w);
        *(uint2*)(smem + NSM_A + m * ROWB + lane * 8) =
            make_uint2(*(uint32_t*)&h0, *(uint32_t*)&h1);
    }
    __syncwarp();
    CP_WAIT0(); __syncthreads();            // B0 (W0a) ready

    stage_b(1, NSM_B1);
    zero_acc();
    mma_pass(NSM_B0);
    write_y(0);                              // y1 (fp16)
    CP_WAIT0(); __syncthreads();             // B1 (W0b) ready

    zero_acc();
    mma_pass(NSM_B1);
    write_y(Y2OFF);                          // y2 (fp16)
}

// ---------------- main fused edge kernel ----------------
extern "C" __global__ void __launch_bounds__(TPB, 2)
edge_mlp_hmma14(float* __restrict__ out,
                const int* __restrict__ ei,
                const float* __restrict__ edge,
                const float* __restrict__ b0, const float* __restrict__ g0, const float* __restrict__ be0,
                const float* __restrict__ b1, const float* __restrict__ g1, const float* __restrict__ be1,
                const float* __restrict__ b2, const float* __restrict__ g2, const float* __restrict__ be2,
                const float* __restrict__ W3, const float* __restrict__ b3,
                int E) {
    extern __shared__ char smem[];
    float* smf = (float*)smem;
    const uint32_t sb = smem_u32(smem);
    const int tid = threadIdx.x, wid = tid >> 5, lane = tid & 31;
    const int base = blockIdx.x * BM;

    // stage LN params + W3/b3 (fp32)
    {
        int i = tid;
        smf[0 * 384 + i] = b0[i]; smf[0 * 384 + 128 + i] = g0[i]; smf[0 * 384 + 256 + i] = be0[i];
        smf[1 * 384 + i] = b1[i]; smf[1 * 384 + 128 + i] = g1[i]; smf[1 * 384 + 256 + i] = be1[i];
        smf[2 * 384 + i] = b2[i]; smf[2 * 384 + 128 + i] = g2[i]; smf[2 * 384 + 256 + i] = be2[i];
        smf[1152 + i] = W3[i];
    }
    if (tid == 0) smf[1280] = b3[0];

    const int arow = (lane & 7) + ((lane >> 3) & 1) * 8;
    const int acol = (lane >> 4) * 8;
    const uint32_t aaddr0 = sb + SM_A + (uint32_t)((wid * 32 + arow) * LDAH + acol) * 2;
    const uint32_t aaddr1 = aaddr0 + 16 * ROWB;
    const int bn = (lane & 7) + ((lane >> 4) & 1) * 8;
    const int bk = ((lane >> 3) & 1) * 8;
    const uint32_t blane = (uint32_t)(bn * LDAH + bk) * 2;

    const int c2 = 2 * (lane & 3);
    const int r4 = lane >> 2;

    float acc[2][16][4];
    uint32_t ah[2][16][2];

    auto zero_acc = [&]() {
#pragma unroll
        for (int a = 0; a < 2; a++)
#pragma unroll
            for (int t = 0; t < 16; t++)
#pragma unroll
                for (int j = 0; j < 4; j++) acc[a][t][j] = 0.f;
    };
    zero_acc();

    auto stage_b = [&](int t, uint32_t dstOff) {
        const char* src = (const char*)(g_wt + t * 16384);
        uint32_t dst = sb + dstOff;
#pragma unroll
        for (int i = 0; i < 16; i++) {
            int u = tid + i * TPB;
            CP_ASYNC16(dst + (u >> 4) * ROWB + (u & 15) * 16, src + u * 16);
        }
        CP_COMMIT();
    };

    // gather edge rows (fp32 -> fp16), warp-local rows; single-use -> streaming
    auto gather_edge = [&]() {
#pragma unroll
        for (int r = 0; r < 32; r++) {
            int m = wid * 32 + r;
            int e = base + m; if (e >= E) e = E - 1;
            float4 v = __ldcs((const float4*)(edge + (size_t)e * H) + lane);
            __half2 h0 = __floats2half2_rn(v.x, v.y);
            __half2 h1 = __floats2half2_rn(v.z, v.w);
            *(uint2*)(smem + SM_A + m * ROWB + lane * 8) =
                make_uint2(*(uint32_t*)&h0, *(uint32_t*)&h1);
        }
        __syncwarp();
    };

    // gather ysum = y1[src] + y2[dst] (fp16 tables, L2-resident) into SM_YS (fp16)
    auto gather_ysum = [&]() {
        int er = base + wid * 32 + lane; if (er >= E) er = E - 1;
        int ns = __ldcs(&ei[er]);
        int nd = __ldcs(&ei[(size_t)E + er]);
#pragma unroll
        for (int r = 0; r < 32; r++) {
            int m = wid * 32 + r;
            int s = __shfl_sync(0xffffffffu, ns, r);
            int d = __shfl_sync(0xffffffffu, nd, r);
            uint2 ua = __ldg((const uint2*)(g_yh + (size_t)s * H) + lane);
            uint2 ub = __ldg((const uint2*)(g_yh + Y2OFF + (size_t)d * H) + lane);
            __half2 a0 = *(__half2*)&ua.x, a1 = *(__half2*)&ua.y;
            __half2 b0_ = *(__half2*)&ub.x, b1_ = *(__half2*)&ub.y;
            float2 fa0 = __half22float2(a0), fa1 = __half22float2(a1);
            float2 fb0 = __half22float2(b0_), fb1 = __half22float2(b1_);
            __half2 s0 = __floats2half2_rn(fa0.x + fb0.x, fa0.y + fb0.y);
            __half2 s1 = __floats2half2_rn(fa1.x + fb1.x, fa1.y + fb1.y);
            *(uint2*)(smem + SM_YS + m * ROWB + lane * 8) =
                make_uint2(*(uint32_t*)&s0, *(uint32_t*)&s1);
        }
        __syncwarp();
    };

    // layer-0 MMA: A streamed from SMEM with prefetch, B ring depth 3
    auto mma_l0 = [&](uint32_t bufAbs) {
        uint32_t A0[4], A1[4], N0[4], N1[4], Bf[3][4];
        uint32_t bb = sb + bufAbs + blane;
        LDMATRIX_X4(A0[0], A0[1], A0[2], A0[3], aaddr0);
        LDMATRIX_X4(A1[0], A1[1], A1[2], A1[3], aaddr1);
        LDMATRIX_X4(Bf[0][0], Bf[0][1], Bf[0][2], Bf[0][3], bb + BOFF(0));
        LDMATRIX_X4(Bf[1][0], Bf[1][1], Bf[1][2], Bf[1][3], bb + BOFF(1));
#pragma unroll
        for (int ks = 0; ks < 8; ks++) {
            if (ks < 7) {
                LDMATRIX_X4(N0[0], N0[1], N0[2], N0[3], aaddr0 + (ks + 1) * 32);
                LDMATRIX_X4(N1[0], N1[1], N1[2], N1[3], aaddr1 + (ks + 1) * 32);
            }
#pragma unroll
            for (int g = 0; g < 8; g++) {
                int t = ks * 8 + g;
                if (t < 62) {
                    int nt = t + 2;
                    LDMATRIX_X4(Bf[nt % 3][0], Bf[nt % 3][1],
                                Bf[nt % 3][2], Bf[nt % 3][3], bb + BOFF(nt));
                }
                const uint32_t* Bc = Bf[t % 3];
                MMA16816(acc[0][2 * g],     A0[0], A0[1], A0[2], A0[3], Bc[0], Bc[1]);
                MMA16816(acc[0][2 * g + 1], A0[0], A0[1], A0[2], A0[3], Bc[2], Bc[3]);
                MMA16816(acc[1][2 * g],     A1[0], A1[1], A1[2], A1[3], Bc[0], Bc[1]);
                MMA16816(acc[1][2 * g + 1], A1[0], A1[1], A1[2], A1[3], Bc[2], Bc[3]);
            }
#pragma unroll
            for (int i = 0; i < 4; i++) { A0[i] = N0[i]; A1[i] = N1[i]; }
        }
    };

    // layers 1-2 MMA: A from ah registers, B ring depth 3
    auto mma_reg = [&](uint32_t bufAbs) {
        uint32_t Bf[3][4];
        uint32_t bb = sb + bufAbs + blane;
        LDMATRIX_X4(Bf[0][0], Bf[0][1], Bf[0][2], Bf[0][3], bb + BOFF(0));
        LDMATRIX_X4(Bf[1][0], Bf[1][1], Bf[1][2], Bf[1][3], bb + BOFF(1));
#pragma unroll
        for (int ks = 0; ks < 8; ks++) {
#pragma unroll
            for (int g = 0; g < 8; g++) {
                int t = ks * 8 + g;
                if (t < 62) {
                    int nt = t + 2;
                    LDMATRIX_X4(Bf[nt % 3][0], Bf[nt % 3][1],
                                Bf[nt % 3][2], Bf[nt % 3][3], bb + BOFF(nt));
                }
                const uint32_t* Bc = Bf[t % 3];
                MMA16816(acc[0][2 * g],     ah[0][2 * ks][0], ah[0][2 * ks][1],
                         ah[0][2 * ks + 1][0], ah[0][2 * ks + 1][1], Bc[0], Bc[1]);
                MMA16816(acc[0][2 * g + 1], ah[0][2 * ks][0], ah[0][2 * ks][1],
                         ah[0][2 * ks + 1][0], ah[0][2 * ks + 1][1], Bc[2], Bc[3]);
                MMA16816(acc[1][2 * g],     ah[1][2 * ks][0], ah[1][2 * ks][1],
                         ah[1][2 * ks + 1][0], ah[1][2 * ks + 1][1], Bc[0], Bc[1]);
                MMA16816(acc[1][2 * g + 1], ah[1][2 * ks][0], ah[1][2 * ks][1],
                         ah[1][2 * ks + 1][0], ah[1][2 * ks + 1][1], Bc[2], Bc[3]);
            }
        }
    };

    // warp-local LN epilogue; l==0 adds fp16 ysum from SM_YS.
    auto epilogue = [&](int l, bool last) {
        const float* pb = smf + l * 384;
        const float* pg = pb + 128;
        const float* pe = pb + 256;
        float s1[2][2], s2[2][2];
#pragma unroll
        for (int am = 0; am < 2; am++)
#pragma unroll
            for (int h = 0; h < 2; h++) { s1[am][h] = 0.f; s2[am][h] = 0.f; }
#pragma unroll
        for (int nt = 0; nt < 16; nt++) {
            int n0 = nt * 8 + c2;
            float bia0 = pb[n0], bia1 = pb[n0 + 1];
#pragma unroll
            for (int am = 0; am < 2; am++)
#pragma unroll
                for (int h = 0; h < 2; h++) {
                    float v0 = acc[am][nt][2 * h]     + bia0;
                    float v1 = acc[am][nt][2 * h + 1] + bia1;
                    if (l == 0) {
                        int row = wid * 32 + am * 16 + h * 8 + r4;
                        __half2 hv = *(__half2*)(smem + SM_YS + row * ROWB + n0 * 2);
                        float2 ys = __half22float2(hv);
                        v0 += ys.x; v1 += ys.y;
                    }
                    acc[am][nt][2 * h] = v0; acc[am][nt][2 * h + 1] = v1;
                    s1[am][h] += v0 + v1;
                    s2[am][h] += v0 * v0 + v1 * v1;
                }
        }
#pragma unroll
        for (int o = 1; o <= 2; o <<= 1)
#pragma unroll
            for (int am = 0; am < 2; am++)
#pragma unroll
                for (int h = 0; h < 2; h++) {
                    s1[am][h] += __shfl_xor_sync(0xffffffffu, s1[am][h], o);
                    s2[am][h] += __shfl_xor_sync(0xffffffffu, s2[am][h], o);
                }
        float mu[2][2], rs[2][2];
#pragma unroll
        for (int am = 0; am < 2; am++)
#pragma unroll
            for (int h = 0; h < 2; h++) {
                float m_ = s1[am][h] * (1.0f / 128.0f);
                mu[am][h] = m_;
                rs[am][h] = rsqrtf(s2[am][h] * (1.0f / 128.0f) - m_ * m_ + LN_EPS);
            }
        if (!last) {
#pragma unroll
            for (int nt = 0; nt < 16; nt++) {
                int n0 = nt * 8 + c2;
                float ga0 = pg[n0], ga1 = pg[n0 + 1];
                float ea0 = pe[n0], ea1 = pe[n0 + 1];
#pragma unroll
                for (int am = 0; am < 2; am++) {
#pragma unroll
                    for (int h = 0; h < 2; h++) {
                        float v0 = fmaxf((acc[am][nt][2 * h]     - mu[am][h]) * rs[am][h] * ga0 + ea0, 0.f);
                        float v1 = fmaxf((acc[am][nt][2 * h + 1] - mu[am][h]) * rs[am][h] * ga1 + ea1, 0.f);
                        __half2 hv = __floats2half2_rn(v0, v1);
                        ah[am][nt][h] = *(uint32_t*)&hv;
                    }
                }
            }
        } else {
            const float* w3 = smf + 1152;
            float p[2][2];
#pragma unroll
            for (int am = 0; am < 2; am++)
#pragma unroll
                for (int h = 0; h < 2; h++) p[am][h] = 0.f;
#pragma unroll
            for (int nt = 0; nt < 16; nt++) {
                int n0 = nt * 8 + c2;
                float ga0 = pg[n0], ga1 = pg[n0 + 1];
                float ea0 = pe[n0], ea1 = pe[n0 + 1];
                float w30 = w3[n0], w31 = w3[n0 + 1];
#pragma unroll
                for (int am = 0; am < 2; am++)
#pragma unroll
                    for (int h = 0; h < 2; h++) {
                        p[am][h] += fmaxf((acc[am][nt][2 * h]     - mu[am][h]) * rs[am][h] * ga0 + ea0, 0.f) * w30
                                  + fmaxf((acc[am][nt][2 * h + 1] - mu[am][h]) * rs[am][h] * ga1 + ea1, 0.f) * w31;
                    }
            }
#pragma unroll
            for (int o = 1; o <= 2; o <<= 1)
#pragma unroll
                for (int am = 0; am < 2; am++)
#pragma unroll
                    for (int h = 0; h < 2; h++)
                        p[am][h] += __shfl_xor_sync(0xffffffffu, p[am][h], o);
            if ((lane & 3) == 0) {
                float bb3 = smf[1280];
#pragma unroll
                for (int am = 0; am < 2; am++)
#pragma unroll
                    for (int h = 0; h < 2; h++) {
                        int row = wid * 32 + am * 16 + h * 8 + r4;
                        int e = base + row;
                        if (e < E) __stcs(&out[e], p[am][h] + bb3);
                    }
            }
        }
    };

    // ---------------- pipeline ----------------
    stage_b(2, SM_B);                  // W0c
    gather_edge();                     // edge -> A (fp16), warp-local
    gather_ysum();                     // ysum -> YS (fp16), warp-local, overlaps
    CP_WAIT0(); __syncthreads();       // W0c ready

    mma_l0(SM_B);                      // acc = edge @ W0c
    __syncthreads();                   // all warps done reading A + B

    stage_b(3, SM_A);                  // W1 -> A region (in flight during epilogue)
    epilogue(0, false);                // acc + ysum + b0, LN, ReLU -> ah
    CP_WAIT0(); __syncthreads();       // W1 ready

    stage_b(4, SM_B);                  // W2 streams during layer-1 MMA
    zero_acc();
    mma_reg(SM_A);                     // W1
    epilogue(1, false);
    CP_WAIT0(); __syncthreads();       // W2 ready; all warps past mma_reg(SM_A)

    zero_acc();
    mma_reg(SM_B);                     // W2
    epilogue(2, true);
}

extern "C" void kernel_launch(void* const* d_in, const int* in_sizes, int n_in,
                              void* d_out, int out_size) {
    const float* x    = (const float*)d_in[0];
    const int*   ei   = (const int*)d_in[1];
    const float* edge = (const float*)d_in[2];
    const float* W0   = (const float*)d_in[3];
    const float* b0   = (const float*)d_in[4];
    const float* g0   = (const float*)d_in[5];
    const float* be0  = (const float*)d_in[6];
    const float* W1   = (const float*)d_in[7];
    const float* b1   = (const float*)d_in[8];
    const float* g1   = (const float*)d_in[9];
    const float* be1  = (const float*)d_in[10];
    const float* W2   = (const float*)d_in[11];
    const float* b2   = (const float*)d_in[12];
    const float* g2   = (const float*)d_in[13];
    const float* be2  = (const float*)d_in[14];
    const float* W3   = (const float*)d_in[15];
    const float* b3   = (const float*)d_in[16];

    int E = out_size;
    int N = in_sizes[0] / H;     // number of nodes

    prep_w<<<(5 * 16384 + 255) / 256, 256>>>(W0, W1, W2);

    cudaFuncSetAttribute(prep_y,
                         cudaFuncAttributeMaxDynamicSharedMemorySize, NSM_TOT);
    prep_y<<<(N + BM - 1) / BM, TPB, NSM_TOT>>>(x, N);

    cudaFuncSetAttribute(edge_mlp_hmma14,
                         cudaFuncAttributeMaxDynamicSharedMemorySize, SM_TOTAL);
    dim3 grid((E + BM - 1) / BM);
    edge_mlp_hmma14<<<grid, TPB, SM_TOTAL>>>(
        (float*)d_out, ei, edge,
        b0, g0, be0, b1, g1, be1, b2, g2, be2, W3, b3, E);
}